// round 15
// baseline (speedup 1.0000x reference)
#include <cuda_runtime.h>
#include <cstdint>

// Problem shape (fixed by the dataset)
#define NLAYERS 60
#define NB 2048
#define NC 128
#define NCOLS (NB * NC)     // 262144 columns
#define COLS_PER_THREAD 2
#define NTHREADS (NCOLS / COLS_PER_THREAD)   // 131072
#define CSTRIDE NTHREADS                     // column stride between reps

#define TPB 128          // threads per block
#define STAGES 4         // smem ring depth
#define PREFETCH 3       // layers in flight ahead of compute

// Exact-op intrinsics: nvcc/ptxas will neither fuse nor split these.
// DO NOT TOUCH — this sequence replicates XLA/LLVM contraction bit-exactly
// (R4: rel_err 1.4e-8). The recursion is chaotic; any change diverges.
#define FMUL(a,b)    __fmul_rn((a),(b))
#define FADD(a,b)    __fadd_rn((a),(b))
#define FSUB(a,b)    __fsub_rn((a),(b))
#define FMA(a,b,c)   __fmaf_rn((a),(b),(c))

// 4-byte async copy gmem->smem (register-free in-flight data).
__device__ __forceinline__ void cpasync4(void* dst_smem, const void* src_gmem) {
    uint32_t d = (uint32_t)__cvta_generic_to_shared(dst_smem);
    asm volatile("cp.async.ca.shared.global [%0], [%1], 4;"
                 :: "r"(d), "l"(src_gmem) : "memory");
}
__device__ __forceinline__ void cp_commit() {
    asm volatile("cp.async.commit_group;" ::: "memory");
}
template <int N>
__device__ __forceinline__ void cp_wait() {
    asm volatile("cp.async.wait_group %0;" :: "n"(N) : "memory");
}

// Stage layout [stage][field][tid]: LDS across a warp is stride-4B -> conflict-free.
// fields: 0=t_d 1=t_df 2=etd 3=erd 4=ead 5=etf 6=erf 7=eaf
struct Smem { float buf[STAGES][8][TPB]; };   // 16 KB

// Issue (possibly empty) copy-group for layer l of column i into stage s.
__device__ __forceinline__ void issue_layer(
    Smem* sm, int s, int l, int i, int tid,
    const float* __restrict__ t_direct,
    const float* __restrict__ t_diffuse,
    const float* __restrict__ es_d,
    const float* __restrict__ es_df)
{
    if (l < NLAYERS) {
        size_t off = (size_t)l * NCOLS + i;
        cpasync4(&sm->buf[s][0][tid], t_direct  + off);
        cpasync4(&sm->buf[s][1][tid], t_diffuse + off);
        const float* pd = es_d  + off * 3;
        const float* pf = es_df + off * 3;
        cpasync4(&sm->buf[s][2][tid], pd + 0);
        cpasync4(&sm->buf[s][3][tid], pd + 1);
        cpasync4(&sm->buf[s][4][tid], pd + 2);
        cpasync4(&sm->buf[s][5][tid], pf + 0);
        cpasync4(&sm->buf[s][6][tid], pf + 1);
        cpasync4(&sm->buf[s][7][tid], pf + 2);
    }
    cp_commit();   // empty group in the tail keeps wait-count arithmetic uniform
}

// Full 60-layer scan of one column, smem-pipelined PREFETCH layers ahead.
__device__ __forceinline__ void scan_column(
    Smem* sm, int tid,
    const float* __restrict__ t_direct,
    const float* __restrict__ t_diffuse,
    const float* __restrict__ es_d,
    const float* __restrict__ es_df,
    const float* __restrict__ r_bottom_direct,
    const float* __restrict__ r_bottom_diffuse,
    const float* __restrict__ a_bottom_direct,
    const float* __restrict__ a_bottom_diffuse,
    float* __restrict__ out, int i)
{
    float r_b_d  = __ldcs(r_bottom_direct  + i);
    float r_b_df = __ldcs(r_bottom_diffuse + i);
    float a_b_d  = __ldcs(a_bottom_direct  + i);
    float a_b_df = __ldcs(a_bottom_diffuse + i);

    // prologue: layers 0..PREFETCH-1 in flight
    #pragma unroll
    for (int s = 0; s < PREFETCH; ++s)
        issue_layer(sm, s, s, i, tid, t_direct, t_diffuse, es_d, es_df);

    #pragma unroll 4
    for (int l = 0; l < NLAYERS; ++l) {
        // keep PREFETCH+1 groups pending, then wait until group l is done
        issue_layer(sm, (l + PREFETCH) % STAGES, l + PREFETCH, i, tid,
                    t_direct, t_diffuse, es_d, es_df);
        cp_wait<PREFETCH>();

        const int s = l % STAGES;
        const float t_d    = sm->buf[s][0][tid];
        const float t_df   = sm->buf[s][1][tid];
        const float e_t_d  = sm->buf[s][2][tid];
        const float e_r_d  = sm->buf[s][3][tid];
        const float e_a_d  = sm->buf[s][4][tid];
        const float e_t_df = sm->buf[s][5][tid];
        const float e_r_df = sm->buf[s][6][tid];
        const float e_a_df = sm->buf[s][7][tid];

        // ===== XLA/LLVM-contracted replica (HLO CSE + DAGCombiner FMA rules) =====
        const float e_d  = FSUB(1.0f, t_d);
        const float e_df = FSUB(1.0f, t_df);

        const float m1  = FMUL(e_df, e_r_df);
        const float m3  = FMUL(t_d,  r_b_d);
        const float m7  = FMUL(e_d,  e_t_d);
        const float m18 = FMUL(e_df, e_t_df);
        const float m20 = FMUL(t_df, r_b_df);

        const float denom = FMA(-m1, r_b_df, 1.0f);
        const float d = __frcp_rn(denom);

        const float s_ = FADD(t_df, m18);

        // ---- direct ----
        const float m4  = FMUL(m3, e_df);
        const float m5  = FMUL(m4, e_r_df);
        const float t_m_d = FMA(m5, d, FMUL(m7, d));

        const float a_bm_d = FMA(t_d, a_b_d, FMUL(t_m_d, a_b_df));

        const float m12 = FMUL(m7, r_b_df);
        const float r_bm_d = FMA(m3, d, FMUL(m12, d));

        const float m15 = FMUL(r_bm_d, e_df);
        const float a_tm_d = FMA(e_d, e_a_d, FMUL(m15, e_a_df));

        const float r_m_d = FMA(e_d, e_r_d, FMUL(r_bm_d, s_));

        // ---- diffuse ----
        const float m21 = FMUL(m20, e_df);
        const float m22 = FMUL(m21, e_r_df);
        const float t_m_df = FMA(m22, d, FMUL(m18, d));

        const float a_bm_df = FMA(t_df, a_b_df, FMUL(t_m_df, a_b_df));

        const float m28 = FMUL(m18, r_b_df);
        const float r_bm_df = FMA(m20, d, FMUL(m28, d));

        const float m31 = FMUL(r_bm_df, e_df);
        const float a_tm_df = FMA(e_df, e_a_df, FMUL(m31, e_a_df));

        const float r_m_df = FMA(r_bm_df, s_, m1);

        // output: [t_m_d, t_m_df, r_bm_d, r_bm_df, a_tm_d, a_tm_df, a_bm_d, a_bm_df]
        float4* o = reinterpret_cast<float4*>(out + ((size_t)l * NCOLS + i) * 8);
        __stcs(o + 0, make_float4(t_m_d,  t_m_df,  r_bm_d,  r_bm_df));
        __stcs(o + 1, make_float4(a_tm_d, a_tm_df, a_bm_d,  a_bm_df));

        // next state
        r_b_d  = r_m_d;
        r_b_df = r_m_df;
        a_b_d  = a_tm_d;
        a_b_df = a_tm_df;
    }
}

// 1024 CTAs x 128 thr = 131072 threads, 2 sequential columns each:
// single balanced wave (R13-validated). Prefetch lives in SMEM (cp.async),
// not registers -> 3 layers in flight without the R14 spill.
__global__ void __launch_bounds__(TPB, 8)
upward_prop_kernel(
    const float* __restrict__ t_direct,
    const float* __restrict__ t_diffuse,
    const float* __restrict__ es_d,
    const float* __restrict__ es_df,
    const float* __restrict__ r_bottom_direct,
    const float* __restrict__ r_bottom_diffuse,
    const float* __restrict__ a_bottom_direct,
    const float* __restrict__ a_bottom_diffuse,
    float* __restrict__ out)  // (L, B, C, 8)
{
    __shared__ Smem sm;
    int tid = threadIdx.x;
    int i = blockIdx.x * TPB + tid;
    if (i >= NTHREADS) return;

    scan_column(&sm, tid, t_direct, t_diffuse, es_d, es_df,
                r_bottom_direct, r_bottom_diffuse,
                a_bottom_direct, a_bottom_diffuse, out, i);
    scan_column(&sm, tid, t_direct, t_diffuse, es_d, es_df,
                r_bottom_direct, r_bottom_diffuse,
                a_bottom_direct, a_bottom_diffuse, out, i + CSTRIDE);
}

extern "C" void kernel_launch(void* const* d_in, const int* in_sizes, int n_in,
                              void* d_out, int out_size)
{
    const float* t_direct   = (const float*)d_in[0];
    const float* t_diffuse  = (const float*)d_in[1];
    const float* es_d       = (const float*)d_in[2];
    const float* es_df      = (const float*)d_in[3];
    const float* r_b_d      = (const float*)d_in[4];
    const float* r_b_df     = (const float*)d_in[5];
    const float* a_b_d      = (const float*)d_in[6];
    const float* a_b_df     = (const float*)d_in[7];
    float* out = (float*)d_out;

    dim3 block(TPB);
    dim3 grid(NTHREADS / TPB);   // 1024 CTAs, single balanced wave
    upward_prop_kernel<<<grid, block>>>(t_direct, t_diffuse, es_d, es_df,
                                        r_b_d, r_b_df, a_b_d, a_b_df, out);
}

// round 16
// speedup vs baseline: 1.0119x; 1.0119x over previous
#include <cuda_runtime.h>
#include <cstdint>

// Problem shape (fixed by the dataset)
#define NLAYERS 60
#define NB 2048
#define NC 128
#define NCOLS (NB * NC)     // 262144 columns
#define COLS_PER_THREAD 2
#define NTHREADS (NCOLS / COLS_PER_THREAD)   // 131072
#define CSTRIDE NTHREADS                     // column stride between reps

// Exact-op intrinsics: nvcc/ptxas will neither fuse nor split these.
// DO NOT TOUCH — this sequence replicates XLA/LLVM contraction bit-exactly
// (R4: rel_err 1.4e-8). The recursion is chaotic; any change diverges.
#define FMUL(a,b)    __fmul_rn((a),(b))
#define FADD(a,b)    __fadd_rn((a),(b))
#define FSUB(a,b)    __fsub_rn((a),(b))
#define FMA(a,b,c)   __fmaf_rn((a),(b),(c))

// Register-free DRAM->L2 prefetch: no dest reg, no scoreboard entry.
__device__ __forceinline__ void prefetch_l2(const void* p) {
    asm volatile("prefetch.global.L2 [%0];" :: "l"(p));
}

struct In8 {
    float t_d, t_df;
    float etd, erd, ead;     // e_split_direct[...,0..2]
    float etf, erf, eaf;     // e_split_diffuse[...,0..2]
};

// Streaming loads: every input byte is read exactly once -> evict-first.
__device__ __forceinline__ void load_layer(
    const float* __restrict__ t_direct,
    const float* __restrict__ t_diffuse,
    const float* __restrict__ es_d,
    const float* __restrict__ es_df,
    int l, int i, In8& v)
{
    size_t off  = (size_t)l * NCOLS + i;
    v.t_d  = __ldcs(t_direct  + off);
    v.t_df = __ldcs(t_diffuse + off);
    const float* pd = es_d  + off * 3;
    const float* pf = es_df + off * 3;
    v.etd = __ldcs(pd + 0);
    v.erd = __ldcs(pd + 1);
    v.ead = __ldcs(pd + 2);
    v.etf = __ldcs(pf + 0);
    v.erf = __ldcs(pf + 1);
    v.eaf = __ldcs(pf + 2);
}

// Full 60-layer scan of one column:
//   registers hold layer l+1 (demand prefetch, R13-validated),
//   L2 prefetch runs 2 layers ahead (register-free MLP).
__device__ __forceinline__ void scan_column(
    const float* __restrict__ t_direct,
    const float* __restrict__ t_diffuse,
    const float* __restrict__ es_d,
    const float* __restrict__ es_df,
    const float* __restrict__ r_bottom_direct,
    const float* __restrict__ r_bottom_diffuse,
    const float* __restrict__ a_bottom_direct,
    const float* __restrict__ a_bottom_diffuse,
    float* __restrict__ out, int i)
{
    float r_b_d  = __ldcs(r_bottom_direct  + i);
    float r_b_df = __ldcs(r_bottom_diffuse + i);
    float a_b_d  = __ldcs(a_bottom_direct  + i);
    float a_b_df = __ldcs(a_bottom_diffuse + i);

    In8 cur, nxt;
    load_layer(t_direct, t_diffuse, es_d, es_df, 0, i, cur);
    // warm L2 for layer 1 too
    {
        size_t off1 = (size_t)1 * NCOLS + i;
        prefetch_l2(t_direct  + off1);
        prefetch_l2(t_diffuse + off1);
        prefetch_l2(es_d  + off1 * 3);
        prefetch_l2(es_df + off1 * 3);
    }

    for (int l = 0; l < NLAYERS; ++l) {
        // L2 prefetch layer l+2 (lane-granular addresses cover every 128B line
        // of the warp's footprint, incl. the 384B es spans)
        if (l + 2 < NLAYERS) {
            size_t off2 = (size_t)(l + 2) * NCOLS + i;
            prefetch_l2(t_direct  + off2);
            prefetch_l2(t_diffuse + off2);
            prefetch_l2(es_d  + off2 * 3);
            prefetch_l2(es_df + off2 * 3);
        }
        // register prefetch layer l+1 (8 loads in flight over this layer's math)
        if (l + 1 < NLAYERS)
            load_layer(t_direct, t_diffuse, es_d, es_df, l + 1, i, nxt);

        const float t_d  = cur.t_d,  t_df = cur.t_df;
        const float e_t_d = cur.etd, e_r_d = cur.erd, e_a_d = cur.ead;
        const float e_t_df = cur.etf, e_r_df = cur.erf, e_a_df = cur.eaf;

        // ===== XLA/LLVM-contracted replica (HLO CSE + DAGCombiner FMA rules) =====
        const float e_d  = FSUB(1.0f, t_d);
        const float e_df = FSUB(1.0f, t_df);

        const float m1  = FMUL(e_df, e_r_df);
        const float m3  = FMUL(t_d,  r_b_d);
        const float m7  = FMUL(e_d,  e_t_d);
        const float m18 = FMUL(e_df, e_t_df);
        const float m20 = FMUL(t_df, r_b_df);

        const float denom = FMA(-m1, r_b_df, 1.0f);
        const float d = __frcp_rn(denom);

        const float s = FADD(t_df, m18);

        // ---- direct ----
        const float m4  = FMUL(m3, e_df);
        const float m5  = FMUL(m4, e_r_df);
        const float t_m_d = FMA(m5, d, FMUL(m7, d));

        const float a_bm_d = FMA(t_d, a_b_d, FMUL(t_m_d, a_b_df));

        const float m12 = FMUL(m7, r_b_df);
        const float r_bm_d = FMA(m3, d, FMUL(m12, d));

        const float m15 = FMUL(r_bm_d, e_df);
        const float a_tm_d = FMA(e_d, e_a_d, FMUL(m15, e_a_df));

        const float r_m_d = FMA(e_d, e_r_d, FMUL(r_bm_d, s));

        // ---- diffuse ----
        const float m21 = FMUL(m20, e_df);
        const float m22 = FMUL(m21, e_r_df);
        const float t_m_df = FMA(m22, d, FMUL(m18, d));

        const float a_bm_df = FMA(t_df, a_b_df, FMUL(t_m_df, a_b_df));

        const float m28 = FMUL(m18, r_b_df);
        const float r_bm_df = FMA(m20, d, FMUL(m28, d));

        const float m31 = FMUL(r_bm_df, e_df);
        const float a_tm_df = FMA(e_df, e_a_df, FMUL(m31, e_a_df));

        const float r_m_df = FMA(r_bm_df, s, m1);

        // output: [t_m_d, t_m_df, r_bm_d, r_bm_df, a_tm_d, a_tm_df, a_bm_d, a_bm_df]
        float4* o = reinterpret_cast<float4*>(out + ((size_t)l * NCOLS + i) * 8);
        __stcs(o + 0, make_float4(t_m_d,  t_m_df,  r_bm_d,  r_bm_df));
        __stcs(o + 1, make_float4(a_tm_d, a_tm_df, a_bm_d,  a_bm_df));

        // next state
        r_b_d  = r_m_d;
        r_b_df = r_m_df;
        a_b_d  = a_tm_d;
        a_b_df = a_tm_df;

        cur = nxt;
    }
}

// 1024 CTAs x 128 thr = 131072 threads; each does exactly 2 columns
// sequentially -> one perfectly balanced wave (R13-validated: harness==ncu).
// 10 CTAs/SM cap keeps the 48-reg budget of the best loop body.
__global__ void __launch_bounds__(128, 10)
upward_prop_kernel(
    const float* __restrict__ t_direct,
    const float* __restrict__ t_diffuse,
    const float* __restrict__ es_d,
    const float* __restrict__ es_df,
    const float* __restrict__ r_bottom_direct,
    const float* __restrict__ r_bottom_diffuse,
    const float* __restrict__ a_bottom_direct,
    const float* __restrict__ a_bottom_diffuse,
    float* __restrict__ out)  // (L, B, C, 8)
{
    int i = blockIdx.x * blockDim.x + threadIdx.x;
    if (i >= NTHREADS) return;

    scan_column(t_direct, t_diffuse, es_d, es_df,
                r_bottom_direct, r_bottom_diffuse,
                a_bottom_direct, a_bottom_diffuse, out, i);
    scan_column(t_direct, t_diffuse, es_d, es_df,
                r_bottom_direct, r_bottom_diffuse,
                a_bottom_direct, a_bottom_diffuse, out, i + CSTRIDE);
}

extern "C" void kernel_launch(void* const* d_in, const int* in_sizes, int n_in,
                              void* d_out, int out_size)
{
    const float* t_direct   = (const float*)d_in[0];
    const float* t_diffuse  = (const float*)d_in[1];
    const float* es_d       = (const float*)d_in[2];
    const float* es_df      = (const float*)d_in[3];
    const float* r_b_d      = (const float*)d_in[4];
    const float* r_b_df     = (const float*)d_in[5];
    const float* a_b_d      = (const float*)d_in[6];
    const float* a_b_df     = (const float*)d_in[7];
    float* out = (float*)d_out;

    dim3 block(128);
    dim3 grid(NTHREADS / 128);   // 1024 CTAs, single balanced wave
    upward_prop_kernel<<<grid, block>>>(t_direct, t_diffuse, es_d, es_df,
                                        r_b_d, r_b_df, a_b_d, a_b_df, out);
}

// round 17
// speedup vs baseline: 1.1448x; 1.1314x over previous
#include <cuda_runtime.h>
#include <cstdint>

// Problem shape (fixed by the dataset)
#define NLAYERS 60
#define NB 2048
#define NC 128
#define NCOLS (NB * NC)     // 262144 columns
#define NTHREADS (NCOLS / 2)   // 131072, each thread owns 2 columns
#define CSTRIDE NTHREADS       // stride between a thread's two columns

// Exact-op intrinsics: nvcc/ptxas will neither fuse nor split these.
// DO NOT TOUCH — this sequence replicates XLA/LLVM contraction bit-exactly
// (R4: rel_err 1.4e-8). The recursion is chaotic; any change diverges.
#define FMUL(a,b)    __fmul_rn((a),(b))
#define FADD(a,b)    __fadd_rn((a),(b))
#define FSUB(a,b)    __fsub_rn((a),(b))
#define FMA(a,b,c)   __fmaf_rn((a),(b),(c))

struct In8 {
    float t_d, t_df;
    float etd, erd, ead;     // e_split_direct[...,0..2]
    float etf, erf, eaf;     // e_split_diffuse[...,0..2]
};

// Streaming loads: every input byte is read exactly once -> evict-first.
__device__ __forceinline__ void load_layer(
    const float* __restrict__ t_direct,
    const float* __restrict__ t_diffuse,
    const float* __restrict__ es_d,
    const float* __restrict__ es_df,
    size_t off, In8& v)
{
    v.t_d  = __ldcs(t_direct  + off);
    v.t_df = __ldcs(t_diffuse + off);
    const float* pd = es_d  + off * 3;
    const float* pf = es_df + off * 3;
    v.etd = __ldcs(pd + 0);
    v.erd = __ldcs(pd + 1);
    v.ead = __ldcs(pd + 2);
    v.etf = __ldcs(pf + 0);
    v.erf = __ldcs(pf + 1);
    v.eaf = __ldcs(pf + 2);
}

// One layer of the frozen XLA/LLVM-contracted recurrence (bit-exact),
// compute + store + state update for one column.
__device__ __forceinline__ void propagate_layer(
    const In8& cur,
    float& r_b_d, float& r_b_df, float& a_b_d, float& a_b_df,
    float* __restrict__ out, size_t off)
{
    const float t_d  = cur.t_d,  t_df = cur.t_df;
    const float e_t_d = cur.etd, e_r_d = cur.erd, e_a_d = cur.ead;
    const float e_t_df = cur.etf, e_r_df = cur.erf, e_a_df = cur.eaf;

    const float e_d  = FSUB(1.0f, t_d);
    const float e_df = FSUB(1.0f, t_df);

    const float m1  = FMUL(e_df, e_r_df);
    const float m3  = FMUL(t_d,  r_b_d);
    const float m7  = FMUL(e_d,  e_t_d);
    const float m18 = FMUL(e_df, e_t_df);
    const float m20 = FMUL(t_df, r_b_df);

    const float denom = FMA(-m1, r_b_df, 1.0f);
    const float d = __frcp_rn(denom);

    const float s = FADD(t_df, m18);

    // ---- direct ----
    const float m4  = FMUL(m3, e_df);
    const float m5  = FMUL(m4, e_r_df);
    const float t_m_d = FMA(m5, d, FMUL(m7, d));

    const float a_bm_d = FMA(t_d, a_b_d, FMUL(t_m_d, a_b_df));

    const float m12 = FMUL(m7, r_b_df);
    const float r_bm_d = FMA(m3, d, FMUL(m12, d));

    const float m15 = FMUL(r_bm_d, e_df);
    const float a_tm_d = FMA(e_d, e_a_d, FMUL(m15, e_a_df));

    const float r_m_d = FMA(e_d, e_r_d, FMUL(r_bm_d, s));

    // ---- diffuse ----
    const float m21 = FMUL(m20, e_df);
    const float m22 = FMUL(m21, e_r_df);
    const float t_m_df = FMA(m22, d, FMUL(m18, d));

    const float a_bm_df = FMA(t_df, a_b_df, FMUL(t_m_df, a_b_df));

    const float m28 = FMUL(m18, r_b_df);
    const float r_bm_df = FMA(m20, d, FMUL(m28, d));

    const float m31 = FMUL(r_bm_df, e_df);
    const float a_tm_df = FMA(e_df, e_a_df, FMUL(m31, e_a_df));

    const float r_m_df = FMA(r_bm_df, s, m1);

    // output: [t_m_d, t_m_df, r_bm_d, r_bm_df, a_tm_d, a_tm_df, a_bm_d, a_bm_df]
    float4* o = reinterpret_cast<float4*>(out + off * 8);
    __stcs(o + 0, make_float4(t_m_d,  t_m_df,  r_bm_d,  r_bm_df));
    __stcs(o + 1, make_float4(a_tm_d, a_tm_df, a_bm_d,  a_bm_df));

    r_b_d  = r_m_d;
    r_b_df = r_m_df;
    a_b_d  = a_tm_d;
    a_b_df = a_tm_df;
}

// 1024 CTAs x 128 thr = 131072 threads, single balanced wave (R13-validated).
// Each thread scans its TWO columns INTERLEAVED in one layer loop: 16
// independent loads issue at the top of each iteration (2x the in-flight
// bytes of the sequential R13 scan), with no explicit prefetch buffers.
__global__ void __launch_bounds__(128, 8)
upward_prop_kernel(
    const float* __restrict__ t_direct,
    const float* __restrict__ t_diffuse,
    const float* __restrict__ es_d,
    const float* __restrict__ es_df,
    const float* __restrict__ r_bottom_direct,
    const float* __restrict__ r_bottom_diffuse,
    const float* __restrict__ a_bottom_direct,
    const float* __restrict__ a_bottom_diffuse,
    float* __restrict__ out)  // (L, B, C, 8)
{
    int i = blockIdx.x * blockDim.x + threadIdx.x;
    if (i >= NTHREADS) return;
    const int j = i + CSTRIDE;

    // scan state, both columns
    float ra_d  = __ldcs(r_bottom_direct  + i);
    float ra_df = __ldcs(r_bottom_diffuse + i);
    float aa_d  = __ldcs(a_bottom_direct  + i);
    float aa_df = __ldcs(a_bottom_diffuse + i);
    float rb_d  = __ldcs(r_bottom_direct  + j);
    float rb_df = __ldcs(r_bottom_diffuse + j);
    float ab_d  = __ldcs(a_bottom_direct  + j);
    float ab_df = __ldcs(a_bottom_diffuse + j);

    #pragma unroll 2
    for (int l = 0; l < NLAYERS; ++l) {
        const size_t base = (size_t)l * NCOLS;
        // 16 independent loads issue back-to-back (front-batched MLP)
        In8 ca, cb;
        load_layer(t_direct, t_diffuse, es_d, es_df, base + i, ca);
        load_layer(t_direct, t_diffuse, es_d, es_df, base + j, cb);

        propagate_layer(ca, ra_d, ra_df, aa_d, aa_df, out, base + i);
        propagate_layer(cb, rb_d, rb_df, ab_d, ab_df, out, base + j);
    }
}

extern "C" void kernel_launch(void* const* d_in, const int* in_sizes, int n_in,
                              void* d_out, int out_size)
{
    const float* t_direct   = (const float*)d_in[0];
    const float* t_diffuse  = (const float*)d_in[1];
    const float* es_d       = (const float*)d_in[2];
    const float* es_df      = (const float*)d_in[3];
    const float* r_b_d      = (const float*)d_in[4];
    const float* r_b_df     = (const float*)d_in[5];
    const float* a_b_d      = (const float*)d_in[6];
    const float* a_b_df     = (const float*)d_in[7];
    float* out = (float*)d_out;

    dim3 block(128);
    dim3 grid(NTHREADS / 128);   // 1024 CTAs, single balanced wave
    upward_prop_kernel<<<grid, block>>>(t_direct, t_diffuse, es_d, es_df,
                                        r_b_d, r_b_df, a_b_d, a_b_df, out);
}